// round 17
// baseline (speedup 1.0000x reference)
#include <cuda_runtime.h>
#include <cuda_fp16.h>
#include <cstdint>

#define TLEN 2048
#define H 20

__device__ __forceinline__ float tanh_hw(float z) {
    float r; asm("tanh.approx.f32 %0, %1;" : "=f"(r) : "f"(z)); return r;
}
__device__ __forceinline__ float sigmoid1(float z) {
    float e; asm("ex2.approx.f32 %0, %1;" : "=f"(e) : "f"(z * -1.4426950408889634f));
    float r; asm("rcp.approx.f32 %0, %1;" : "=f"(r) : "f"(e + 1.0f));
    return r;
}
// pack two f32 into f16x2: lower half = lo, upper half = hi
__device__ __forceinline__ uint32_t pkhf(float lo, float hi) {
    uint32_t w; asm("cvt.rn.f16x2.f32 %0, %1, %2;" : "=r"(w) : "f"(hi), "f"(lo)); return w;
}
// D += A(16x16 f16) * B(16x8 f16, col-major); baseline PTX (sm_80+)
__device__ __forceinline__ void mma16816(float* c, const uint32_t* a, const uint32_t* b) {
    asm volatile(
        "mma.sync.aligned.m16n8k16.row.col.f32.f16.f16.f32 "
        "{%0,%1,%2,%3}, {%4,%5,%6,%7}, {%8,%9}, {%0,%1,%2,%3};"
        : "+f"(c[0]), "+f"(c[1]), "+f"(c[2]), "+f"(c[3])
        : "r"(a[0]), "r"(a[1]), "r"(a[2]), "r"(a[3]), "r"(b[0]), "r"(b[1]));
}

// R17 = R16 (fragment-closed mma.sync RNN) with the 4-deep MMA accumulate
// chain split into TWO PARALLEL 2-deep chains per (tile, n-tile):
//   P = (hi.k0 -> lo.k1) seeded with x-projection; Q = (hi.k1 -> lo.k0) seeded 0
//   c = P + Q -> tanh -> cvt -> A fragments (no shuffles/smem: D/A layouts match)
// and bf16 -> fp16 everywhere (8x less h-quantization noise, same speed).
// R16 measured the binder as the per-warp serial chain (~123 cyc/substep,
// issue 19.5%); this cuts it to ~85. Grid 512 x 32, zero smem.
__global__ void __launch_bounds__(32) rnn_tc(
    const float* __restrict__ x,      // [B, TLEN]
    const float* __restrict__ W_ih,   // [H]
    const float* __restrict__ W_hh,   // [H, H]
    const float* __restrict__ b_ih,   // [H]
    const float* __restrict__ b_hh,   // [H]
    const float* __restrict__ W_fc,   // [H]
    const float* __restrict__ b_fc,   // [1]
    float* __restrict__ out)          // [B]
{
    const int lane = threadIdx.x & 31;
    const int g  = lane >> 2;          // fragment group row 0..7
    const int tg = lane & 3;           // thread-in-group 0..3
    const int base = blockIdx.x * 32;  // 32 batches per warp

    // ---- B fragments: [ktile][ntile][hi/lo][2 regs] ----
    // b0 = {B[2t][g], B[2t+1][g]}, b1 = {B[2t+8][g], B[2t+9][g]}; B[k][n]=W[8j+g][k]
    uint32_t Bf[2][3][2][2];
    #pragma unroll
    for (int kt = 0; kt < 2; kt++) {
        #pragma unroll
        for (int j = 0; j < 3; j++) {
            const int r = 8 * j + g;
            const int k0 = 16 * kt + 2 * tg;
            float whi[4], wlo[4];
            #pragma unroll
            for (int e = 0; e < 4; e++) {
                const int k = k0 + (e >> 1) * 8 + (e & 1);
                float w = (r < H && k < H) ? W_hh[r * H + k] : 0.0f;
                __half hb = __float2half(w);
                whi[e] = __half2float(hb);
                wlo[e] = w - whi[e];
            }
            Bf[kt][j][0][0] = pkhf(whi[0], whi[1]);
            Bf[kt][j][0][1] = pkhf(whi[2], whi[3]);
            Bf[kt][j][1][0] = pkhf(wlo[0], wlo[1]);
            Bf[kt][j][1][1] = pkhf(wlo[2], wlo[3]);
        }
    }

    // ---- per-lane column constants (cols 8j + 2t + i) ----
    float wihc[3][2], prec[3][2], wfcc[3][2];
    #pragma unroll
    for (int j = 0; j < 3; j++)
        #pragma unroll
        for (int i = 0; i < 2; i++) {
            const int c = 8 * j + 2 * tg + i;
            const bool v = (c < H);
            wihc[j][i] = v ? W_ih[c] : 0.0f;
            prec[j][i] = v ? (b_ih[c] + b_hh[c]) : 0.0f;
            wfcc[j][i] = v ? W_fc[c] : 0.0f;
        }
    const float bfc = b_fc[0];

    // ---- x streams: rows g, g+8 of each tile ----
    const float* xp0 = x + (size_t)(base + g) * TLEN;
    const float* xp1 = x + (size_t)(base + g + 8) * TLEN;
    const float* xp2 = x + (size_t)(base + 16 + g) * TLEN;
    const float* xp3 = x + (size_t)(base + 24 + g) * TLEN;

    uint32_t A0[2][4], A1[2][4];       // [ktile][reg] per tile
    #pragma unroll
    for (int r = 0; r < 4; r++) { A0[0][r] = A0[1][r] = A1[0][r] = A1[1][r] = 0u; }
    float th0[12], th1[12];

    for (int t = 0; t < TLEN; t += 4) {
        const float4 v0 = *(const float4*)(xp0 + t);
        const float4 v1 = *(const float4*)(xp1 + t);
        const float4 v2 = *(const float4*)(xp2 + t);
        const float4 v3 = *(const float4*)(xp3 + t);
        const float xs0[4] = {v0.x, v0.y, v0.z, v0.w};
        const float xs1[4] = {v1.x, v1.y, v1.z, v1.w};
        const float xs2[4] = {v2.x, v2.y, v2.z, v2.w};
        const float xs3[4] = {v3.x, v3.y, v3.z, v3.w};

        #pragma unroll
        for (int s = 0; s < 4; s++) {
            // chain P seeded with x-projection; chain Q seeded with 0
            float p0[3][4], q0[3][4], p1[3][4], q1[3][4];
            #pragma unroll
            for (int j = 0; j < 3; j++) {
                p0[j][0] = fmaf(xs0[s], wihc[j][0], prec[j][0]);
                p0[j][1] = fmaf(xs0[s], wihc[j][1], prec[j][1]);
                p0[j][2] = fmaf(xs1[s], wihc[j][0], prec[j][0]);
                p0[j][3] = fmaf(xs1[s], wihc[j][1], prec[j][1]);
                p1[j][0] = fmaf(xs2[s], wihc[j][0], prec[j][0]);
                p1[j][1] = fmaf(xs2[s], wihc[j][1], prec[j][1]);
                p1[j][2] = fmaf(xs3[s], wihc[j][0], prec[j][0]);
                p1[j][3] = fmaf(xs3[s], wihc[j][1], prec[j][1]);
                #pragma unroll
                for (int i = 0; i < 4; i++) { q0[j][i] = 0.0f; q1[j][i] = 0.0f; }
            }
            // level 1: all 12 first-level MMAs independent
            #pragma unroll
            for (int j = 0; j < 3; j++) {
                mma16816(p0[j], A0[0], Bf[0][j][0]);   // P: hi.k0
                mma16816(q0[j], A0[1], Bf[1][j][0]);   // Q: hi.k1
                mma16816(p1[j], A1[0], Bf[0][j][0]);
                mma16816(q1[j], A1[1], Bf[1][j][0]);
            }
            // level 2
            #pragma unroll
            for (int j = 0; j < 3; j++) {
                mma16816(p0[j], A0[1], Bf[1][j][1]);   // P: lo.k1
                mma16816(q0[j], A0[0], Bf[0][j][1]);   // Q: lo.k0
                mma16816(p1[j], A1[1], Bf[1][j][1]);
                mma16816(q1[j], A1[0], Bf[0][j][1]);
            }
            #pragma unroll
            for (int j = 0; j < 3; j++)
                #pragma unroll
                for (int i = 0; i < 4; i++) {
                    th0[j * 4 + i] = tanh_hw(p0[j][i] + q0[j][i]);
                    th1[j * 4 + i] = tanh_hw(p1[j][i] + q1[j][i]);
                }
            // D -> A (fragment-closed)
            A0[0][0] = pkhf(th0[0], th0[1]);   A0[0][1] = pkhf(th0[2],  th0[3]);
            A0[0][2] = pkhf(th0[4], th0[5]);   A0[0][3] = pkhf(th0[6],  th0[7]);
            A0[1][0] = pkhf(th0[8], th0[9]);   A0[1][1] = pkhf(th0[10], th0[11]);
            A0[1][2] = 0u;                     A0[1][3] = 0u;
            A1[0][0] = pkhf(th1[0], th1[1]);   A1[0][1] = pkhf(th1[2],  th1[3]);
            A1[0][2] = pkhf(th1[4], th1[5]);   A1[0][3] = pkhf(th1[6],  th1[7]);
            A1[1][0] = pkhf(th1[8], th1[9]);   A1[1][1] = pkhf(th1[10], th1[11]);
            A1[1][2] = 0u;                     A1[1][3] = 0u;
        }
    }

    // ---- FC head + sigmoid from f32 tanh outputs ----
    float pA0 = 0.f, pB0 = 0.f, pA1 = 0.f, pB1 = 0.f;
    #pragma unroll
    for (int j = 0; j < 3; j++)
        #pragma unroll
        for (int i = 0; i < 2; i++) {
            pA0 = fmaf(th0[j * 4 + i],     wfcc[j][i], pA0);
            pB0 = fmaf(th0[j * 4 + 2 + i], wfcc[j][i], pB0);
            pA1 = fmaf(th1[j * 4 + i],     wfcc[j][i], pA1);
            pB1 = fmaf(th1[j * 4 + 2 + i], wfcc[j][i], pB1);
        }
    #pragma unroll
    for (int d = 1; d < 4; d <<= 1) {
        pA0 += __shfl_xor_sync(0xffffffffu, pA0, d, 32);
        pB0 += __shfl_xor_sync(0xffffffffu, pB0, d, 32);
        pA1 += __shfl_xor_sync(0xffffffffu, pA1, d, 32);
        pB1 += __shfl_xor_sync(0xffffffffu, pB1, d, 32);
    }
    if (tg == 0) {
        out[base + g]      = sigmoid1(pA0 + bfc);
        out[base + g + 8]  = sigmoid1(pB0 + bfc);
        out[base + 16 + g] = sigmoid1(pA1 + bfc);
        out[base + 24 + g] = sigmoid1(pB1 + bfc);
    }
}

extern "C" void kernel_launch(void* const* d_in, const int* in_sizes, int n_in,
                              void* d_out, int out_size) {
    const float* x    = (const float*)d_in[0];
    const float* W_ih = (const float*)d_in[1];
    const float* W_hh = (const float*)d_in[2];
    const float* b_ih = (const float*)d_in[3];
    const float* b_hh = (const float*)d_in[4];
    const float* W_fc = (const float*)d_in[5];
    const float* b_fc = (const float*)d_in[6];
    float* out = (float*)d_out;

    const int B = in_sizes[0] / TLEN;   // 16384
    const int blocks = B / 32;          // 512 warps, 2 MMA tiles each
    rnn_tc<<<blocks, 32>>>(x, W_ih, W_hh, b_ih, b_hh, W_fc, b_fc, out);
}